// round 3
// baseline (speedup 1.0000x reference)
#include <cuda_runtime.h>
#include <cuda_bf16.h>
#include <cstdint>

// loss = || sum_spatial(input_c) - sum_spatial(target_c) ||^2 / C^2
// input/target: (1, 128, 512, 512) fp32 contiguous.
// Single fused kernel, streaming loads (__ldcs), last-block finalize.

#define NCH   128
#define HW    (512 * 512)          // 262144 elements per channel
#define SPLIT 16                   // blocks per channel
#define NBLK  (NCH * SPLIT)        // 2048 blocks
#define NTHR  256

__device__ float        g_partial[NBLK];
__device__ unsigned int g_count;   // zero-init at load; last block resets it

__global__ __launch_bounds__(NTHR) void fused_loss_kernel(
    const float4* __restrict__ in, const float4* __restrict__ tgt,
    float* __restrict__ out)
{
    const int blk = blockIdx.x;              // 0 .. NBLK-1
    const int c   = blk >> 4;                // channel
    const int s   = blk & (SPLIT - 1);       // split within channel

    const int vec_per_chan = HW / 4;                 // 65536 float4/channel
    const int vec_per_blk  = vec_per_chan / SPLIT;   // 4096 float4/block

    const size_t base = (size_t)c * vec_per_chan + (size_t)s * vec_per_blk;
    const float4* pa = in  + base;
    const float4* pb = tgt + base;

    float acc0 = 0.0f, acc1 = 0.0f;
    // 16 float4 per thread per array; unroll 4 -> 8 LDG.128 batched (MLP),
    // streaming (.cs, evict-first) since data is read exactly once.
    #pragma unroll 4
    for (int i = threadIdx.x; i < vec_per_blk; i += NTHR) {
        float4 a = __ldcs(pa + i);
        float4 b = __ldcs(pb + i);
        acc0 += (a.x - b.x) + (a.y - b.y);
        acc1 += (a.z - b.z) + (a.w - b.w);
    }
    float acc = acc0 + acc1;

    // ---- block reduction ----
    __shared__ float sm[NTHR / 32];
    #pragma unroll
    for (int o = 16; o > 0; o >>= 1)
        acc += __shfl_down_sync(0xffffffffu, acc, o);
    if ((threadIdx.x & 31) == 0) sm[threadIdx.x >> 5] = acc;
    __syncthreads();

    __shared__ bool s_last;
    if (threadIdx.x == 0) {
        float v = 0.0f;
        #pragma unroll
        for (int w = 0; w < NTHR / 32; w++) v += sm[w];
        g_partial[blk] = v;
        __threadfence();                                // publish partial
        unsigned int t = atomicAdd(&g_count, 1u);
        s_last = (t == (unsigned int)(NBLK - 1));
    }
    __syncthreads();

    // ---- last block finalizes (deterministic fixed-order sums) ----
    if (s_last) {
        float v = 0.0f;
        if (threadIdx.x < NCH) {                        // one thread / channel
            float d = 0.0f;
            #pragma unroll
            for (int k = 0; k < SPLIT; k++)
                d += g_partial[threadIdx.x * SPLIT + k];
            v = d * d;
        }
        // reduce 128 squared values (threads >= NCH contribute 0)
        #pragma unroll
        for (int o = 16; o > 0; o >>= 1)
            v += __shfl_down_sync(0xffffffffu, v, o);
        if ((threadIdx.x & 31) == 0) sm[threadIdx.x >> 5] = v;
        __syncthreads();
        if (threadIdx.x == 0) {
            float t = sm[0] + sm[1] + sm[2] + sm[3];
            out[0] = t * (1.0f / (128.0f * 128.0f));
            g_count = 0;                                // reset for graph replay
        }
    }
}

extern "C" void kernel_launch(void* const* d_in, const int* in_sizes, int n_in,
                              void* d_out, int out_size)
{
    const float4* in  = (const float4*)d_in[0];
    const float4* tgt = (const float4*)d_in[1];
    float* out = (float*)d_out;

    fused_loss_kernel<<<NBLK, NTHR>>>(in, tgt, out);
}

// round 4
// speedup vs baseline: 1.0471x; 1.0471x over previous
#include <cuda_runtime.h>
#include <cuda_bf16.h>
#include <cstdint>

// loss = || sum_spatial(input_c) - sum_spatial(target_c) ||^2 / C^2
// input/target: (1, 128, 512, 512) fp32 contiguous.
// Single fused kernel. Each block streams ONE contiguous 128KB run of ONE
// array (better DRAM row locality than interleaving two streams 512MB apart);
// finalize combines in/tgt partials per channel in fixed order.

#define NCH    128
#define HW     (512 * 512)           // 262144 elements per channel
#define SPLIT  8                     // blocks per channel per array
#define HALF   (NCH * SPLIT)         // 1024 blocks per array
#define NBLK   (2 * HALF)            // 2048 blocks total
#define NTHR   256

__device__ float        g_partial[NBLK];   // [0,1024): in, [1024,2048): tgt
__device__ unsigned int g_count;           // zero-init; last block resets

__global__ __launch_bounds__(NTHR) void fused_loss_kernel(
    const float4* __restrict__ in, const float4* __restrict__ tgt,
    float* __restrict__ out)
{
    const int blk    = blockIdx.x;             // 0 .. NBLK-1
    const int half   = blk >> 10;              // 0 = in, 1 = tgt
    const int sub    = blk & (HALF - 1);       // 0 .. 1023
    const int c      = sub >> 3;               // channel
    const int s      = sub & (SPLIT - 1);      // split within channel

    const int vec_per_chan = HW / 4;                 // 65536 float4/channel
    const int vec_per_blk  = vec_per_chan / SPLIT;   // 8192 float4/block

    const float4* src = half ? tgt : in;
    const float4* p = src + (size_t)c * vec_per_chan + (size_t)s * vec_per_blk;

    // 32 float4 per thread; unroll 8 -> 8 independent LDG.128 in flight.
    float acc0 = 0.0f, acc1 = 0.0f;
    #pragma unroll 8
    for (int i = threadIdx.x; i < vec_per_blk; i += NTHR) {
        float4 a = __ldg(p + i);
        acc0 += a.x + a.y;
        acc1 += a.z + a.w;
    }
    float acc = acc0 + acc1;

    // ---- block reduction ----
    __shared__ float sm[NTHR / 32];
    #pragma unroll
    for (int o = 16; o > 0; o >>= 1)
        acc += __shfl_down_sync(0xffffffffu, acc, o);
    if ((threadIdx.x & 31) == 0) sm[threadIdx.x >> 5] = acc;
    __syncthreads();

    __shared__ bool s_last;
    if (threadIdx.x == 0) {
        float v = 0.0f;
        #pragma unroll
        for (int w = 0; w < NTHR / 32; w++) v += sm[w];
        g_partial[blk] = v;
        __threadfence();                                // publish partial
        unsigned int t = atomicAdd(&g_count, 1u);
        s_last = (t == (unsigned int)(NBLK - 1));
    }
    __syncthreads();

    // ---- last block finalizes (deterministic fixed-order sums) ----
    if (s_last) {
        float v = 0.0f;
        if (threadIdx.x < NCH) {                        // one thread / channel
            float d = 0.0f;
            #pragma unroll
            for (int k = 0; k < SPLIT; k++)
                d += g_partial[threadIdx.x * SPLIT + k];            // in
            #pragma unroll
            for (int k = 0; k < SPLIT; k++)
                d -= g_partial[HALF + threadIdx.x * SPLIT + k];     // tgt
            v = d * d;
        }
        #pragma unroll
        for (int o = 16; o > 0; o >>= 1)
            v += __shfl_down_sync(0xffffffffu, v, o);
        if ((threadIdx.x & 31) == 0) sm[threadIdx.x >> 5] = v;
        __syncthreads();
        if (threadIdx.x == 0) {
            float t = sm[0] + sm[1] + sm[2] + sm[3];
            out[0] = t * (1.0f / (128.0f * 128.0f));
            g_count = 0;                                // reset for graph replay
        }
    }
}

extern "C" void kernel_launch(void* const* d_in, const int* in_sizes, int n_in,
                              void* d_out, int out_size)
{
    const float4* in  = (const float4*)d_in[0];
    const float4* tgt = (const float4*)d_in[1];
    float* out = (float*)d_out;

    fused_loss_kernel<<<NBLK, NTHR>>>(in, tgt, out);
}